// round 2
// baseline (speedup 1.0000x reference)
#include <cuda_runtime.h>

#define LOG2E 1.4426950408889634f

// ---------------- scratch (device globals; no allocation allowed) -------------
__device__ float g_k[32 * 2 * 2048];     // [c][b][n]
__device__ float g_q[32 * 2048 * 2];     // [c][n][b]
__device__ float g_v[32 * 2048 * 2];     // [c][n][b]
__device__ float g_vz[32 * 2048 * 2];    // v * (1/Z) per column
__device__ float g_nm[32 * 2048];        // -(max logit)*log2e per (c,m)
__device__ float g_attn[32 * 2048 * 2];  // flat [C,N,B] attention output

// =============================================================================
// Kernel A: fused conv3d for key/query/value (64 -> 3x32 channels, 3x3x3, pad 1)
// grid (cog=8, d=8, b=2), 192 threads = 12 co x 16 h, each thread does a W-row.
// =============================================================================
__global__ __launch_bounds__(192) void conv_qkv_kernel(
    const float* __restrict__ x,
    const float* __restrict__ wk, const float* __restrict__ bk,
    const float* __restrict__ wq, const float* __restrict__ bq,
    const float* __restrict__ wv, const float* __restrict__ bv)
{
    __shared__ float tile[3 * 18 * 18];   // one input channel, d/h/w halo, zero-padded
    const int t   = threadIdx.x;
    const int b   = blockIdx.z;
    const int d   = blockIdx.y;
    const int cog = blockIdx.x;
    const int co  = cog * 12 + (t >> 4);  // 0..95
    const int h   = t & 15;
    const int which = co >> 5;            // 0=key 1=query 2=value
    const int c     = co & 31;

    const float* W  = (which == 0) ? wk : (which == 1 ? wq : wv);
    const float* Bs = (which == 0) ? bk : (which == 1 ? bq : bv);

    float acc[16];
    {
        const float bias = Bs[c];
        #pragma unroll
        for (int w = 0; w < 16; w++) acc[w] = bias;
    }
    const float* Wc = W + c * 64 * 27;

    for (int ci = 0; ci < 64; ci++) {
        __syncthreads();
        for (int i = t; i < 972; i += 192) {
            int dd = i / 324, r = i % 324, hh = r / 18, ww = r % 18;
            int gd = d + dd - 1, gh = hh - 1, gw = ww - 1;
            float val = 0.f;
            if ((unsigned)gd < 8u && (unsigned)gh < 16u && (unsigned)gw < 16u)
                val = x[(((b * 64 + ci) * 8 + gd) * 16 + gh) * 16 + gw];
            tile[i] = val;
        }
        __syncthreads();
        const float* Wci = Wc + ci * 27;
        #pragma unroll
        for (int kd = 0; kd < 3; kd++) {
            #pragma unroll
            for (int kh = 0; kh < 3; kh++) {
                const float* row = &tile[(kd * 18 + h + kh) * 18];
                float r0[18];
                #pragma unroll
                for (int j = 0; j < 18; j++) r0[j] = row[j];
                const float w0 = Wci[(kd * 3 + kh) * 3 + 0];
                const float w1 = Wci[(kd * 3 + kh) * 3 + 1];
                const float w2 = Wci[(kd * 3 + kh) * 3 + 2];
                #pragma unroll
                for (int w = 0; w < 16; w++)
                    acc[w] = fmaf(w0, r0[w], fmaf(w1, r0[w + 1], fmaf(w2, r0[w + 2], acc[w])));
            }
        }
    }

    const int nbase = d * 256 + h * 16;
    if (which == 0) {
        #pragma unroll
        for (int w = 0; w < 16; w++)
            g_k[(c * 2 + b) * 2048 + nbase + w] = acc[w];
    } else {
        float* dst = (which == 1) ? g_q : g_v;
        #pragma unroll
        for (int w = 0; w < 16; w++)
            dst[(c * 2048 + nbase + w) * 2 + b] = acc[w];
    }
}

// =============================================================================
// Kernel B: per-column softmax stats. softmax is over the ROW axis n (axis=1),
// i.e. normalized per column m. Rank-2 logits: s = q(n).k(m), dim 2.
// Works in log2 domain. Also folds 1/Z into V.
// grid (mchunk=8, c=32), 256 threads, 1 column per thread.
// =============================================================================
__global__ __launch_bounds__(256) void colstats_kernel()
{
    __shared__ float2 sq[2048];   // q[c][n][0..1]
    const int t = threadIdx.x;
    const int c = blockIdx.y;
    const int m = blockIdx.x * 256 + t;

    const float2* qsrc = (const float2*)(g_q + c * 4096);
    for (int i = t; i < 2048; i += 256) sq[i] = qsrc[i];
    __syncthreads();

    const float k0 = g_k[(c * 2 + 0) * 2048 + m] * LOG2E;
    const float k1 = g_k[(c * 2 + 1) * 2048 + m] * LOG2E;

    float M = -1e30f;
    #pragma unroll 8
    for (int n = 0; n < 2048; n++) {
        float2 q = sq[n];
        float s = fmaf(q.x, k0, q.y * k1);
        M = fmaxf(M, s);
    }
    float Z = 0.f;
    #pragma unroll 4
    for (int n = 0; n < 2048; n++) {
        float2 q = sq[n];
        float s = fmaf(q.x, k0, fmaf(q.y, k1, -M));
        float e;
        asm("ex2.approx.ftz.f32 %0, %1;" : "=f"(e) : "f"(s));
        Z += e;
    }
    const float invZ = 1.f / Z;
    g_nm[c * 2048 + m] = -M;
    g_vz[(c * 2048 + m) * 2 + 0] = g_v[(c * 2048 + m) * 2 + 0] * invZ;
    g_vz[(c * 2048 + m) * 2 + 1] = g_v[(c * 2048 + m) * 2 + 1] * invZ;
}

// =============================================================================
// Kernel C: out[c,n,b] = sum_m 2^(s2[n,m] - M2[m]) * vz[m,b]
// grid (nchunk=8, c=32), 256 threads, 1 row per thread.
// Inner loop: LDS.128 + LDS.64 + 2 FFMA + EX2 + 2 FFMA.
// =============================================================================
__global__ __launch_bounds__(256) void attn_out_kernel()
{
    __shared__ float4 ksm[2048];  // (k0*log2e, k1*log2e, -M2, pad)  32KB
    __shared__ float2 vzs[2048];  //                                 16KB
    const int t = threadIdx.x;
    const int c = blockIdx.y;
    const int n = blockIdx.x * 256 + t;

    for (int i = t; i < 2048; i += 256) {
        ksm[i] = make_float4(g_k[(c * 2 + 0) * 2048 + i] * LOG2E,
                             g_k[(c * 2 + 1) * 2048 + i] * LOG2E,
                             g_nm[c * 2048 + i], 0.f);
        vzs[i] = ((const float2*)(g_vz + c * 4096))[i];
    }
    __syncthreads();

    const float2 qn = ((const float2*)(g_q + c * 4096))[n];
    float a0 = 0.f, a1 = 0.f;
    #pragma unroll 4
    for (int m = 0; m < 2048; m++) {
        float4 kk = ksm[m];
        float s = fmaf(qn.x, kk.x, fmaf(qn.y, kk.y, kk.z));
        float e;
        asm("ex2.approx.ftz.f32 %0, %1;" : "=f"(e) : "f"(s));
        float2 vv = vzs[m];
        a0 = fmaf(e, vv.x, a0);
        a1 = fmaf(e, vv.y, a1);
    }
    ((float2*)(g_attn + c * 4096))[n] = make_float2(a0, a1);
}

// =============================================================================
// Kernel D: conv_alter (32 -> 64, 3x3x3, pad 1) + bias + residual.
// Input is g_attn flat [C,N,B] REINTERPRETED as [B,32,D,H,W] (the torch .view):
// element (b,ci,n) lives at flat index (b*32+ci)*2048 + n.
// grid (cog=8, d=8, b=2), 128 threads = 8 co x 16 h.
// =============================================================================
__global__ __launch_bounds__(128) void conv_alter_kernel(
    const float* __restrict__ x,
    const float* __restrict__ wa, const float* __restrict__ ba,
    float* __restrict__ out)
{
    __shared__ float tile[3 * 18 * 18];
    const int t   = threadIdx.x;
    const int b   = blockIdx.z;
    const int d   = blockIdx.y;
    const int cog = blockIdx.x;
    const int co  = cog * 8 + (t >> 4);   // 0..63
    const int h   = t & 15;

    float acc[16];
    {
        const float bias = ba[co];
        #pragma unroll
        for (int w = 0; w < 16; w++) acc[w] = bias;
    }
    const float* Wc = wa + co * 32 * 27;

    for (int ci = 0; ci < 32; ci++) {
        __syncthreads();
        for (int i = t; i < 972; i += 128) {
            int dd = i / 324, r = i % 324, hh = r / 18, ww = r % 18;
            int gd = d + dd - 1, gh = hh - 1, gw = ww - 1;
            float val = 0.f;
            if ((unsigned)gd < 8u && (unsigned)gh < 16u && (unsigned)gw < 16u)
                val = g_attn[(b * 32 + ci) * 2048 + gd * 256 + gh * 16 + gw];
            tile[i] = val;
        }
        __syncthreads();
        const float* Wci = Wc + ci * 27;
        #pragma unroll
        for (int kd = 0; kd < 3; kd++) {
            #pragma unroll
            for (int kh = 0; kh < 3; kh++) {
                const float* row = &tile[(kd * 18 + h + kh) * 18];
                float r0[18];
                #pragma unroll
                for (int j = 0; j < 18; j++) r0[j] = row[j];
                const float w0 = Wci[(kd * 3 + kh) * 3 + 0];
                const float w1 = Wci[(kd * 3 + kh) * 3 + 1];
                const float w2 = Wci[(kd * 3 + kh) * 3 + 2];
                #pragma unroll
                for (int w = 0; w < 16; w++)
                    acc[w] = fmaf(w0, r0[w], fmaf(w1, r0[w + 1], fmaf(w2, r0[w + 2], acc[w])));
            }
        }
    }

    const int nbase = d * 256 + h * 16;
    #pragma unroll
    for (int w = 0; w < 16; w++) {
        const int idx = (b * 64 + co) * 2048 + nbase + w;
        out[idx] = x[idx] + acc[w];
    }
}

// =============================================================================
extern "C" void kernel_launch(void* const* d_in, const int* in_sizes, int n_in,
                              void* d_out, int out_size)
{
    const float* x  = (const float*)d_in[0];
    const float* wk = (const float*)d_in[1];
    const float* bk = (const float*)d_in[2];
    const float* wq = (const float*)d_in[3];
    const float* bq = (const float*)d_in[4];
    const float* wv = (const float*)d_in[5];
    const float* bv = (const float*)d_in[6];
    const float* wa = (const float*)d_in[7];
    const float* ba = (const float*)d_in[8];
    float* out = (float*)d_out;

    conv_qkv_kernel<<<dim3(8, 8, 2), 192>>>(x, wk, bk, wq, bq, wv, bv);
    colstats_kernel<<<dim3(8, 32), 256>>>();
    attn_out_kernel<<<dim3(8, 32), 256>>>();
    conv_alter_kernel<<<dim3(8, 8, 2), 128>>>(x, wa, ba, out);
}

// round 3
// speedup vs baseline: 1.6605x; 1.6605x over previous
#include <cuda_runtime.h>

#define LOG2E 1.4426950408889634f

// ---------------- scratch (device globals; no allocation allowed) -------------
__device__ float g_k[32 * 2 * 2048];     // [c][b][n]           (raw)
__device__ float g_q[32 * 2048 * 2];     // [c][n][b]           (pre-scaled by LOG2E)
__device__ float g_v[32 * 2048 * 2];     // [c][n][b]
__device__ float g_vz[32 * 2048 * 2];    // v * (1/Z) per column
__device__ float g_nm[32 * 2048];        // -(max log2-logit) per (c,m)
__device__ float g_attn[32 * 2048 * 2];  // flat [C,N,B] attention output

// =============================================================================
// Kernel 0: init biases into qkv scratch, and out = x + b_alter (residual+bias).
// Conv kernels then pure-accumulate via atomicAdd.
// =============================================================================
__global__ __launch_bounds__(256) void init_kernel(
    const float* __restrict__ x,
    const float* __restrict__ bk, const float* __restrict__ bq,
    const float* __restrict__ bv, const float* __restrict__ ba,
    float* __restrict__ out)
{
    const int i = blockIdx.x * 256 + threadIdx.x;   // grid covers 131072
    if (i < 131072) {
        const int c = i >> 12;                      // both layouts: flat/4096 = channel
        g_k[i] = bk[c];
        g_q[i] = bq[c] * LOG2E;
        g_v[i] = bv[c];
    }
    for (int j = i; j < 262144; j += gridDim.x * 256) {
        const int co = (j >> 11) & 63;
        out[j] = x[j] + ba[co];
    }
}

// =============================================================================
// Kernel A: conv3d for key/query/value (64 -> 3x32 ch, 3x3x3, pad 1), split-K.
// grid (cog=8, d=8, z=8: b*4 + ci-split), 192 threads = 12 co x 16 h.
// Each block accumulates 16 input channels, atomicAdds into scratch.
// =============================================================================
__global__ __launch_bounds__(192) void conv_qkv_kernel(
    const float* __restrict__ x,
    const float* __restrict__ wk, const float* __restrict__ wq,
    const float* __restrict__ wv)
{
    __shared__ float tile[3 * 18 * 18];   // one input channel, d/h/w halo, zero-padded
    const int t   = threadIdx.x;
    const int b   = blockIdx.z >> 2;
    const int s   = blockIdx.z & 3;       // ci chunk: [16s, 16s+16)
    const int d   = blockIdx.y;
    const int cog = blockIdx.x;
    const int co  = cog * 12 + (t >> 4);  // 0..95
    const int h   = t & 15;
    const int which = co >> 5;            // 0=key 1=query 2=value
    const int c     = co & 31;

    const float* W = (which == 0) ? wk : (which == 1 ? wq : wv);
    float acc[16];
    #pragma unroll
    for (int w = 0; w < 16; w++) acc[w] = 0.f;

    const float* Wc = W + c * 64 * 27 + s * 16 * 27;

    for (int ci = 0; ci < 16; ci++) {
        const int cig = s * 16 + ci;
        __syncthreads();
        for (int i = t; i < 972; i += 192) {
            int dd = i / 324, r = i % 324, hh = r / 18, ww = r % 18;
            int gd = d + dd - 1, gh = hh - 1, gw = ww - 1;
            float val = 0.f;
            if ((unsigned)gd < 8u && (unsigned)gh < 16u && (unsigned)gw < 16u)
                val = x[(((b * 64 + cig) * 8 + gd) * 16 + gh) * 16 + gw];
            tile[i] = val;
        }
        __syncthreads();
        const float* Wci = Wc + ci * 27;
        #pragma unroll
        for (int kd = 0; kd < 3; kd++) {
            #pragma unroll
            for (int kh = 0; kh < 3; kh++) {
                const float* row = &tile[(kd * 18 + h + kh) * 18];
                float r0[18];
                #pragma unroll
                for (int j = 0; j < 18; j++) r0[j] = row[j];
                const float w0 = Wci[(kd * 3 + kh) * 3 + 0];
                const float w1 = Wci[(kd * 3 + kh) * 3 + 1];
                const float w2 = Wci[(kd * 3 + kh) * 3 + 2];
                #pragma unroll
                for (int w = 0; w < 16; w++)
                    acc[w] = fmaf(w0, r0[w], fmaf(w1, r0[w + 1], fmaf(w2, r0[w + 2], acc[w])));
            }
        }
    }

    const int nbase = d * 256 + h * 16;
    if (which == 0) {
        #pragma unroll
        for (int w = 0; w < 16; w++)
            atomicAdd(&g_k[(c * 2 + b) * 2048 + nbase + w], acc[w]);
    } else {
        float* dst = (which == 1) ? g_q : g_v;
        const float sc = (which == 1) ? LOG2E : 1.f;
        #pragma unroll
        for (int w = 0; w < 16; w++)
            atomicAdd(&dst[(c * 2048 + nbase + w) * 2 + b], acc[w] * sc);
    }
}

// =============================================================================
// Kernel B: per-column softmax stats in log2 domain (q pre-scaled by LOG2E).
// softmax axis = n (rows); stats per column m. Folds 1/Z into V.
// grid (mchunk=8, c=32), 256 threads, 1 column per thread.
// =============================================================================
__global__ __launch_bounds__(256) void colstats_kernel()
{
    __shared__ float2 sq[2048];   // q[c][n][0..1] (log2-scaled)
    const int t = threadIdx.x;
    const int c = blockIdx.y;
    const int m = blockIdx.x * 256 + t;

    const float2* qsrc = (const float2*)(g_q + c * 4096);
    for (int i = t; i < 2048; i += 256) sq[i] = qsrc[i];
    __syncthreads();

    const float k0 = g_k[(c * 2 + 0) * 2048 + m];
    const float k1 = g_k[(c * 2 + 1) * 2048 + m];

    float M = -1e30f;
    #pragma unroll 8
    for (int n = 0; n < 2048; n++) {
        float2 q = sq[n];
        float sv = fmaf(q.x, k0, q.y * k1);
        M = fmaxf(M, sv);
    }
    float Z = 0.f;
    #pragma unroll 4
    for (int n = 0; n < 2048; n++) {
        float2 q = sq[n];
        float sv = fmaf(q.x, k0, fmaf(q.y, k1, -M));
        float e;
        asm("ex2.approx.ftz.f32 %0, %1;" : "=f"(e) : "f"(sv));
        Z += e;
    }
    const float invZ = 1.f / Z;
    g_nm[c * 2048 + m] = -M;
    g_vz[(c * 2048 + m) * 2 + 0] = g_v[(c * 2048 + m) * 2 + 0] * invZ;
    g_vz[(c * 2048 + m) * 2 + 1] = g_v[(c * 2048 + m) * 2 + 1] * invZ;
}

// =============================================================================
// Kernel C: out[c,n,b] = sum_m 2^(q(n).k(m) - M(m)) * vz[m,b]   (log2 domain)
// grid (nchunk=8, c=32), 256 threads, 1 row per thread.
// =============================================================================
__global__ __launch_bounds__(256) void attn_out_kernel()
{
    __shared__ float4 ksm[2048];  // (k0, k1, -M, pad)  32KB
    __shared__ float2 vzs[2048];  //                    16KB
    const int t = threadIdx.x;
    const int c = blockIdx.y;
    const int n = blockIdx.x * 256 + t;

    for (int i = t; i < 2048; i += 256) {
        ksm[i] = make_float4(g_k[(c * 2 + 0) * 2048 + i],
                             g_k[(c * 2 + 1) * 2048 + i],
                             g_nm[c * 2048 + i], 0.f);
        vzs[i] = ((const float2*)(g_vz + c * 4096))[i];
    }
    __syncthreads();

    const float2 qn = ((const float2*)(g_q + c * 4096))[n];
    float a0 = 0.f, a1 = 0.f;
    #pragma unroll 4
    for (int m = 0; m < 2048; m++) {
        float4 kk = ksm[m];
        float sv = fmaf(qn.x, kk.x, fmaf(qn.y, kk.y, kk.z));
        float e;
        asm("ex2.approx.ftz.f32 %0, %1;" : "=f"(e) : "f"(sv));
        float2 vv = vzs[m];
        a0 = fmaf(e, vv.x, a0);
        a1 = fmaf(e, vv.y, a1);
    }
    ((float2*)(g_attn + c * 4096))[n] = make_float2(a0, a1);
}

// =============================================================================
// Kernel D: conv_alter (32 -> 64, 3x3x3, pad 1), split-K, accumulate into
// out (pre-initialized to x + bias by init_kernel).
// Input g_attn flat [C,N,B] reinterpreted as [B,32,D,H,W] (the torch .view).
// grid (cog=8, d=8, z=8: b*4 + ci-split), 128 threads = 8 co x 16 h.
// =============================================================================
__global__ __launch_bounds__(128) void conv_alter_kernel(
    const float* __restrict__ wa, float* __restrict__ out)
{
    __shared__ float tile[3 * 18 * 18];
    const int t   = threadIdx.x;
    const int b   = blockIdx.z >> 2;
    const int s   = blockIdx.z & 3;       // ci chunk: [8s, 8s+8)
    const int d   = blockIdx.y;
    const int cog = blockIdx.x;
    const int co  = cog * 8 + (t >> 4);   // 0..63
    const int h   = t & 15;

    float acc[16];
    #pragma unroll
    for (int w = 0; w < 16; w++) acc[w] = 0.f;
    const float* Wc = wa + co * 32 * 27 + s * 8 * 27;

    for (int ci = 0; ci < 8; ci++) {
        const int cig = s * 8 + ci;
        __syncthreads();
        for (int i = t; i < 972; i += 128) {
            int dd = i / 324, r = i % 324, hh = r / 18, ww = r % 18;
            int gd = d + dd - 1, gh = hh - 1, gw = ww - 1;
            float val = 0.f;
            if ((unsigned)gd < 8u && (unsigned)gh < 16u && (unsigned)gw < 16u)
                val = g_attn[(b * 32 + cig) * 2048 + gd * 256 + gh * 16 + gw];
            tile[i] = val;
        }
        __syncthreads();
        const float* Wci = Wc + ci * 27;
        #pragma unroll
        for (int kd = 0; kd < 3; kd++) {
            #pragma unroll
            for (int kh = 0; kh < 3; kh++) {
                const float* row = &tile[(kd * 18 + h + kh) * 18];
                float r0[18];
                #pragma unroll
                for (int j = 0; j < 18; j++) r0[j] = row[j];
                const float w0 = Wci[(kd * 3 + kh) * 3 + 0];
                const float w1 = Wci[(kd * 3 + kh) * 3 + 1];
                const float w2 = Wci[(kd * 3 + kh) * 3 + 2];
                #pragma unroll
                for (int w = 0; w < 16; w++)
                    acc[w] = fmaf(w0, r0[w], fmaf(w1, r0[w + 1], fmaf(w2, r0[w + 2], acc[w])));
            }
        }
    }

    const int nbase = d * 256 + h * 16;
    #pragma unroll
    for (int w = 0; w < 16; w++)
        atomicAdd(&out[(b * 64 + co) * 2048 + nbase + w], acc[w]);
}

// =============================================================================
extern "C" void kernel_launch(void* const* d_in, const int* in_sizes, int n_in,
                              void* d_out, int out_size)
{
    const float* x  = (const float*)d_in[0];
    const float* wk = (const float*)d_in[1];
    const float* bk = (const float*)d_in[2];
    const float* wq = (const float*)d_in[3];
    const float* bq = (const float*)d_in[4];
    const float* wv = (const float*)d_in[5];
    const float* bv = (const float*)d_in[6];
    const float* wa = (const float*)d_in[7];
    const float* ba = (const float*)d_in[8];
    float* out = (float*)d_out;

    init_kernel<<<512, 256>>>(x, bk, bq, bv, ba, out);
    conv_qkv_kernel<<<dim3(8, 8, 8), 192>>>(x, wk, wq, wv);
    colstats_kernel<<<dim3(8, 32), 256>>>();
    attn_out_kernel<<<dim3(8, 32), 256>>>();
    conv_alter_kernel<<<dim3(8, 8, 8), 128>>>(wa, out);
}

// round 4
// speedup vs baseline: 1.7952x; 1.0811x over previous
#include <cuda_runtime.h>

#define LOG2E 1.4426950408889634f

// ---------------- scratch (device globals; no allocation allowed) -------------
__device__ float g_k[32 * 2 * 2048];     // [c][b][n]           (raw)
__device__ float g_q[32 * 2048 * 2];     // [c][n][b]           (pre-scaled by LOG2E)
__device__ float g_v[32 * 2048 * 2];     // [c][n][b]
__device__ float g_vz[32 * 2048 * 2];    // v * (1/Z) per column
__device__ float g_nm[32 * 2048];        // -(box-bound max log2-logit) per (c,m)
__device__ float g_attn[32 * 2048 * 2];  // flat [C,N,B] attention output

// =============================================================================
// Kernel 0: init biases into qkv scratch, out = x + b_alter, zero g_attn.
// =============================================================================
__global__ __launch_bounds__(256) void init_kernel(
    const float* __restrict__ x,
    const float* __restrict__ bk, const float* __restrict__ bq,
    const float* __restrict__ bv, const float* __restrict__ ba,
    float* __restrict__ out)
{
    const int i = blockIdx.x * 256 + threadIdx.x;   // 512 blocks -> 131072 threads
    if (i < 131072) {
        const int c = i >> 12;
        g_k[i] = bk[c];
        g_q[i] = bq[c] * LOG2E;
        g_v[i] = bv[c];
    }
    for (int j = i; j < 262144; j += 131072) {
        const int co = (j >> 11) & 63;
        out[j] = x[j] + ba[co];
        g_attn[j] = 0.f;
    }
}

// =============================================================================
// Kernel A: conv3d key/query/value (64 -> 3x32 ch, 3x3x3, pad 1), split-K x4.
// grid (cog=8, d=8, z=8: b*4 + s), 192 threads = 12 co x 16 h.
// Tile rows padded to 20 floats so row loads are 4xLDS.128 + LDS.64.
// =============================================================================
__global__ __launch_bounds__(192) void conv_qkv_kernel(
    const float* __restrict__ x,
    const float* __restrict__ wk, const float* __restrict__ wq,
    const float* __restrict__ wv)
{
    __shared__ float tile[3 * 18 * 20];   // padded: [dd][hh][20]
    const int t   = threadIdx.x;
    const int b   = blockIdx.z >> 2;
    const int s   = blockIdx.z & 3;       // ci chunk: [16s, 16s+16)
    const int d   = blockIdx.y;
    const int cog = blockIdx.x;
    const int co  = cog * 12 + (t >> 4);  // 0..95
    const int h   = t & 15;
    const int which = co >> 5;            // 0=key 1=query 2=value
    const int c     = co & 31;

    const float* W = (which == 0) ? wk : (which == 1 ? wq : wv);
    float acc[16];
    #pragma unroll
    for (int w = 0; w < 16; w++) acc[w] = 0.f;

    const float* Wc = W + c * 64 * 27 + s * 16 * 27;

    for (int ci = 0; ci < 16; ci++) {
        const int cig = s * 16 + ci;
        __syncthreads();
        for (int i = t; i < 972; i += 192) {
            int dd = i / 324, r = i % 324, hh = r / 18, ww = r % 18;
            int gd = d + dd - 1, gh = hh - 1, gw = ww - 1;
            float val = 0.f;
            if ((unsigned)gd < 8u && (unsigned)gh < 16u && (unsigned)gw < 16u)
                val = x[(((b * 64 + cig) * 8 + gd) * 16 + gh) * 16 + gw];
            tile[dd * 360 + hh * 20 + ww] = val;
        }
        __syncthreads();
        const float* Wci = Wc + ci * 27;
        #pragma unroll
        for (int kd = 0; kd < 3; kd++) {
            #pragma unroll
            for (int kh = 0; kh < 3; kh++) {
                const float* row = &tile[kd * 360 + (h + kh) * 20];
                float4 ra = ((const float4*)row)[0];
                float4 rb = ((const float4*)row)[1];
                float4 rc = ((const float4*)row)[2];
                float4 rd = ((const float4*)row)[3];
                float2 re = *(const float2*)(row + 16);
                float r0[18] = {ra.x, ra.y, ra.z, ra.w, rb.x, rb.y, rb.z, rb.w,
                                rc.x, rc.y, rc.z, rc.w, rd.x, rd.y, rd.z, rd.w,
                                re.x, re.y};
                const float w0 = Wci[(kd * 3 + kh) * 3 + 0];
                const float w1 = Wci[(kd * 3 + kh) * 3 + 1];
                const float w2 = Wci[(kd * 3 + kh) * 3 + 2];
                #pragma unroll
                for (int w = 0; w < 16; w++)
                    acc[w] = fmaf(w0, r0[w], fmaf(w1, r0[w + 1], fmaf(w2, r0[w + 2], acc[w])));
            }
        }
    }

    const int nbase = d * 256 + h * 16;
    if (which == 0) {
        #pragma unroll
        for (int w = 0; w < 16; w++)
            atomicAdd(&g_k[(c * 2 + b) * 2048 + nbase + w], acc[w]);
    } else {
        float* dst = (which == 1) ? g_q : g_v;
        const float sc = (which == 1) ? LOG2E : 1.f;
        #pragma unroll
        for (int w = 0; w < 16; w++)
            atomicAdd(&dst[(c * 2048 + nbase + w) * 2 + b], acc[w] * sc);
    }
}

// =============================================================================
// Kernel B: per-column Z in log2 domain with BOX-BOUND shift (no max pass).
// Softmax is shift-invariant; M-hat only prevents overflow.
// grid (16 mchunk, c=32), 128 threads, 1 column per thread.
// =============================================================================
__global__ __launch_bounds__(128) void colstats_kernel()
{
    __shared__ float2 sq[2048];
    __shared__ float4 red[4];
    __shared__ float4 smm;
    const int t = threadIdx.x;
    const int c = blockIdx.y;
    const int m = blockIdx.x * 128 + t;

    const float2* qsrc = (const float2*)(g_q + c * 4096);
    float mxx = -1e30f, mnx = 1e30f, mxy = -1e30f, mny = 1e30f;
    for (int i = t; i < 2048; i += 128) {
        float2 q = qsrc[i];
        sq[i] = q;
        mxx = fmaxf(mxx, q.x); mnx = fminf(mnx, q.x);
        mxy = fmaxf(mxy, q.y); mny = fminf(mny, q.y);
    }
    #pragma unroll
    for (int off = 16; off; off >>= 1) {
        mxx = fmaxf(mxx, __shfl_xor_sync(~0u, mxx, off));
        mnx = fminf(mnx, __shfl_xor_sync(~0u, mnx, off));
        mxy = fmaxf(mxy, __shfl_xor_sync(~0u, mxy, off));
        mny = fminf(mny, __shfl_xor_sync(~0u, mny, off));
    }
    if ((t & 31) == 0) red[t >> 5] = make_float4(mxx, mnx, mxy, mny);
    __syncthreads();
    if (t == 0) {
        float4 a = red[0];
        #pragma unroll
        for (int w = 1; w < 4; w++) {
            float4 bb = red[w];
            a.x = fmaxf(a.x, bb.x); a.y = fminf(a.y, bb.y);
            a.z = fmaxf(a.z, bb.z); a.w = fminf(a.w, bb.w);
        }
        smm = a;
    }
    __syncthreads();

    const float k0 = g_k[(c * 2 + 0) * 2048 + m];
    const float k1 = g_k[(c * 2 + 1) * 2048 + m];
    const float4 mm = smm;
    const float M = fmaxf(k0 * mm.x, k0 * mm.y) + fmaxf(k1 * mm.z, k1 * mm.w);

    float Z = 0.f;
    #pragma unroll 8
    for (int n = 0; n < 2048; n++) {
        float2 q = sq[n];
        float sv = fmaf(q.x, k0, fmaf(q.y, k1, -M));
        float e;
        asm("ex2.approx.ftz.f32 %0, %1;" : "=f"(e) : "f"(sv));
        Z += e;
    }
    const float invZ = 1.f / Z;
    g_nm[c * 2048 + m] = -M;
    g_vz[(c * 2048 + m) * 2 + 0] = g_v[(c * 2048 + m) * 2 + 0] * invZ;
    g_vz[(c * 2048 + m) * 2 + 1] = g_v[(c * 2048 + m) * 2 + 1] * invZ;
}

// =============================================================================
// Kernel C: out[c,n,b] += sum_{m in half} 2^(q.k - M) * vz[m,b]  (m-split x2)
// grid (8 nchunk, 2 mhalf, 32 c), 256 threads, 1 row per thread.
// Two atomic contributors per output -> commutative -> deterministic.
// =============================================================================
__global__ __launch_bounds__(256) void attn_out_kernel()
{
    __shared__ float4 ksm[1024];  // (k0, k1, -M, pad)  16KB
    __shared__ float2 vzs[1024];  //                     8KB
    const int t  = threadIdx.x;
    const int c  = blockIdx.z;
    const int m0 = blockIdx.y * 1024;
    const int n  = blockIdx.x * 256 + t;

    for (int i = t; i < 1024; i += 256) {
        const int m = m0 + i;
        ksm[i] = make_float4(g_k[(c * 2 + 0) * 2048 + m],
                             g_k[(c * 2 + 1) * 2048 + m],
                             g_nm[c * 2048 + m], 0.f);
        vzs[i] = ((const float2*)(g_vz + c * 4096))[m];
    }
    __syncthreads();

    const float2 qn = ((const float2*)(g_q + c * 4096))[n];
    float a0 = 0.f, a1 = 0.f;
    #pragma unroll 4
    for (int m = 0; m < 1024; m++) {
        float4 kk = ksm[m];
        float sv = fmaf(qn.x, kk.x, fmaf(qn.y, kk.y, kk.z));
        float e;
        asm("ex2.approx.ftz.f32 %0, %1;" : "=f"(e) : "f"(sv));
        float2 vv = vzs[m];
        a0 = fmaf(e, vv.x, a0);
        a1 = fmaf(e, vv.y, a1);
    }
    atomicAdd(&g_attn[c * 4096 + n * 2 + 0], a0);
    atomicAdd(&g_attn[c * 4096 + n * 2 + 1], a1);
}

// =============================================================================
// Kernel D: conv_alter (32 -> 64, 3x3x3, pad 1), split-K x8, accumulate into
// out (pre-initialized to x + bias). g_attn flat [C,N,B] viewed as [B,32,D,H,W].
// grid (cog=8, d=8, z=16: b*8 + s), 128 threads = 8 co x 16 h.
// =============================================================================
__global__ __launch_bounds__(128) void conv_alter_kernel(
    const float* __restrict__ wa, float* __restrict__ out)
{
    __shared__ float tile[3 * 18 * 20];
    const int t   = threadIdx.x;
    const int b   = blockIdx.z >> 3;
    const int s   = blockIdx.z & 7;       // ci chunk: [4s, 4s+4)
    const int d   = blockIdx.y;
    const int cog = blockIdx.x;
    const int co  = cog * 8 + (t >> 4);   // 0..63
    const int h   = t & 15;

    float acc[16];
    #pragma unroll
    for (int w = 0; w < 16; w++) acc[w] = 0.f;
    const float* Wc = wa + co * 32 * 27 + s * 4 * 27;

    for (int ci = 0; ci < 4; ci++) {
        const int cig = s * 4 + ci;
        __syncthreads();
        for (int i = t; i < 972; i += 128) {
            int dd = i / 324, r = i % 324, hh = r / 18, ww = r % 18;
            int gd = d + dd - 1, gh = hh - 1, gw = ww - 1;
            float val = 0.f;
            if ((unsigned)gd < 8u && (unsigned)gh < 16u && (unsigned)gw < 16u)
                val = g_attn[(b * 32 + cig) * 2048 + gd * 256 + gh * 16 + gw];
            tile[dd * 360 + hh * 20 + ww] = val;
        }
        __syncthreads();
        const float* Wci = Wc + ci * 27;
        #pragma unroll
        for (int kd = 0; kd < 3; kd++) {
            #pragma unroll
            for (int kh = 0; kh < 3; kh++) {
                const float* row = &tile[kd * 360 + (h + kh) * 20];
                float4 ra = ((const float4*)row)[0];
                float4 rb = ((const float4*)row)[1];
                float4 rc = ((const float4*)row)[2];
                float4 rd = ((const float4*)row)[3];
                float2 re = *(const float2*)(row + 16);
                float r0[18] = {ra.x, ra.y, ra.z, ra.w, rb.x, rb.y, rb.z, rb.w,
                                rc.x, rc.y, rc.z, rc.w, rd.x, rd.y, rd.z, rd.w,
                                re.x, re.y};
                const float w0 = Wci[(kd * 3 + kh) * 3 + 0];
                const float w1 = Wci[(kd * 3 + kh) * 3 + 1];
                const float w2 = Wci[(kd * 3 + kh) * 3 + 2];
                #pragma unroll
                for (int w = 0; w < 16; w++)
                    acc[w] = fmaf(w0, r0[w], fmaf(w1, r0[w + 1], fmaf(w2, r0[w + 2], acc[w])));
            }
        }
    }

    const int nbase = d * 256 + h * 16;
    #pragma unroll
    for (int w = 0; w < 16; w++)
        atomicAdd(&out[(b * 64 + co) * 2048 + nbase + w], acc[w]);
}

// =============================================================================
extern "C" void kernel_launch(void* const* d_in, const int* in_sizes, int n_in,
                              void* d_out, int out_size)
{
    const float* x  = (const float*)d_in[0];
    const float* wk = (const float*)d_in[1];
    const float* bk = (const float*)d_in[2];
    const float* wq = (const float*)d_in[3];
    const float* bq = (const float*)d_in[4];
    const float* wv = (const float*)d_in[5];
    const float* bv = (const float*)d_in[6];
    const float* wa = (const float*)d_in[7];
    const float* ba = (const float*)d_in[8];
    float* out = (float*)d_out;

    init_kernel<<<512, 256>>>(x, bk, bq, bv, ba, out);
    conv_qkv_kernel<<<dim3(8, 8, 8), 192>>>(x, wk, wq, wv);
    colstats_kernel<<<dim3(16, 32), 128>>>();
    attn_out_kernel<<<dim3(8, 2, 32), 256>>>();
    conv_alter_kernel<<<dim3(8, 8, 16), 128>>>(wa, out);
}

// round 5
// speedup vs baseline: 1.9048x; 1.0611x over previous
#include <cuda_runtime.h>

#define LOG2E 1.4426950408889634f

// ---------------- scratch (device globals; no allocation allowed) -------------
__device__ float g_k[32 * 2 * 2048];     // [c][b][n]           (raw)
__device__ float g_q[32 * 2048 * 2];     // [c][n][b]           (pre-scaled by LOG2E)
__device__ float g_v[32 * 2048 * 2];     // [c][n][b]
__device__ float g_vz[32 * 2048 * 2];    // v * (1/Z) per column
__device__ float g_nm[32 * 2048];        // -(box-bound max log2-logit) per (c,m)
__device__ float g_attn[32 * 2048 * 2];  // flat [C,N,B] attention output

// =============================================================================
// Kernel 0: init biases into qkv scratch, out = x + b_alter, zero g_attn.
// =============================================================================
__global__ __launch_bounds__(256) void init_kernel(
    const float* __restrict__ x,
    const float* __restrict__ bk, const float* __restrict__ bq,
    const float* __restrict__ bv, const float* __restrict__ ba,
    float* __restrict__ out)
{
    const int i = blockIdx.x * 256 + threadIdx.x;   // 512 blocks -> 131072 threads
    if (i < 131072) {
        const int c = i >> 12;
        g_k[i] = bk[c];
        g_q[i] = bq[c] * LOG2E;
        g_v[i] = bv[c];
    }
    for (int j = i; j < 262144; j += 131072) {
        const int co = (j >> 11) & 63;
        out[j] = x[j] + ba[co];
        g_attn[j] = 0.f;
    }
}

// =============================================================================
// Kernel A: conv3d key/query/value (64 -> 3x32 ch, 3x3x3, pad 1), split-K x4.
// grid (cog=8, d=8, z=8: b*4 + s), 192 threads = 12 co x 16 h.
// =============================================================================
__global__ __launch_bounds__(192) void conv_qkv_kernel(
    const float* __restrict__ x,
    const float* __restrict__ wk, const float* __restrict__ wq,
    const float* __restrict__ wv)
{
    __shared__ float tile[3 * 18 * 20];   // padded: [dd][hh][20]
    const int t   = threadIdx.x;
    const int b   = blockIdx.z >> 2;
    const int s   = blockIdx.z & 3;       // ci chunk: [16s, 16s+16)
    const int d   = blockIdx.y;
    const int cog = blockIdx.x;
    const int co  = cog * 12 + (t >> 4);  // 0..95
    const int h   = t & 15;
    const int which = co >> 5;            // 0=key 1=query 2=value
    const int c     = co & 31;

    const float* W = (which == 0) ? wk : (which == 1 ? wq : wv);
    float acc[16];
    #pragma unroll
    for (int w = 0; w < 16; w++) acc[w] = 0.f;

    const float* Wc = W + c * 64 * 27 + s * 16 * 27;

    for (int ci = 0; ci < 16; ci++) {
        const int cig = s * 16 + ci;
        __syncthreads();
        for (int i = t; i < 972; i += 192) {
            int dd = i / 324, r = i % 324, hh = r / 18, ww = r % 18;
            int gd = d + dd - 1, gh = hh - 1, gw = ww - 1;
            float val = 0.f;
            if ((unsigned)gd < 8u && (unsigned)gh < 16u && (unsigned)gw < 16u)
                val = x[(((b * 64 + cig) * 8 + gd) * 16 + gh) * 16 + gw];
            tile[dd * 360 + hh * 20 + ww] = val;
        }
        __syncthreads();
        const float* Wci = Wc + ci * 27;
        #pragma unroll
        for (int kd = 0; kd < 3; kd++) {
            #pragma unroll
            for (int kh = 0; kh < 3; kh++) {
                const float* row = &tile[kd * 360 + (h + kh) * 20];
                float4 ra = ((const float4*)row)[0];
                float4 rb = ((const float4*)row)[1];
                float4 rc = ((const float4*)row)[2];
                float4 rd = ((const float4*)row)[3];
                float2 re = *(const float2*)(row + 16);
                float r0[18] = {ra.x, ra.y, ra.z, ra.w, rb.x, rb.y, rb.z, rb.w,
                                rc.x, rc.y, rc.z, rc.w, rd.x, rd.y, rd.z, rd.w,
                                re.x, re.y};
                const float w0 = Wci[(kd * 3 + kh) * 3 + 0];
                const float w1 = Wci[(kd * 3 + kh) * 3 + 1];
                const float w2 = Wci[(kd * 3 + kh) * 3 + 2];
                #pragma unroll
                for (int w = 0; w < 16; w++)
                    acc[w] = fmaf(w0, r0[w], fmaf(w1, r0[w + 1], fmaf(w2, r0[w + 2], acc[w])));
            }
        }
    }

    const int nbase = d * 256 + h * 16;
    if (which == 0) {
        #pragma unroll
        for (int w = 0; w < 16; w++)
            atomicAdd(&g_k[(c * 2 + b) * 2048 + nbase + w], acc[w]);
    } else {
        float* dst = (which == 1) ? g_q : g_v;
        const float sc = (which == 1) ? LOG2E : 1.f;
        #pragma unroll
        for (int w = 0; w < 16; w++)
            atomicAdd(&dst[(c * 2048 + nbase + w) * 2 + b], acc[w] * sc);
    }
}

// =============================================================================
// Kernel B: per-column Z in log2 domain with BOX-BOUND shift (no max pass).
// 2 columns per thread: 1 LDS.64 feeds 2 exp elements.
// grid (8 mchunk, c=32), 128 threads.
// =============================================================================
__global__ __launch_bounds__(128) void colstats_kernel()
{
    __shared__ float2 sq[2048];
    __shared__ float4 red[4];
    __shared__ float4 smm;
    const int t = threadIdx.x;
    const int c = blockIdx.y;
    const int ma = blockIdx.x * 256 + t;
    const int mb = ma + 128;

    const float2* qsrc = (const float2*)(g_q + c * 4096);
    float mxx = -1e30f, mnx = 1e30f, mxy = -1e30f, mny = 1e30f;
    for (int i = t; i < 2048; i += 128) {
        float2 q = qsrc[i];
        sq[i] = q;
        mxx = fmaxf(mxx, q.x); mnx = fminf(mnx, q.x);
        mxy = fmaxf(mxy, q.y); mny = fminf(mny, q.y);
    }
    #pragma unroll
    for (int off = 16; off; off >>= 1) {
        mxx = fmaxf(mxx, __shfl_xor_sync(~0u, mxx, off));
        mnx = fminf(mnx, __shfl_xor_sync(~0u, mnx, off));
        mxy = fmaxf(mxy, __shfl_xor_sync(~0u, mxy, off));
        mny = fminf(mny, __shfl_xor_sync(~0u, mny, off));
    }
    if ((t & 31) == 0) red[t >> 5] = make_float4(mxx, mnx, mxy, mny);
    __syncthreads();
    if (t == 0) {
        float4 a = red[0];
        #pragma unroll
        for (int w = 1; w < 4; w++) {
            float4 bb = red[w];
            a.x = fmaxf(a.x, bb.x); a.y = fminf(a.y, bb.y);
            a.z = fmaxf(a.z, bb.z); a.w = fminf(a.w, bb.w);
        }
        smm = a;
    }
    __syncthreads();

    const float4 mm = smm;
    const float k0a = g_k[(c * 2 + 0) * 2048 + ma];
    const float k1a = g_k[(c * 2 + 1) * 2048 + ma];
    const float k0b = g_k[(c * 2 + 0) * 2048 + mb];
    const float k1b = g_k[(c * 2 + 1) * 2048 + mb];
    const float Ma = fmaxf(k0a * mm.x, k0a * mm.y) + fmaxf(k1a * mm.z, k1a * mm.w);
    const float Mb = fmaxf(k0b * mm.x, k0b * mm.y) + fmaxf(k1b * mm.z, k1b * mm.w);

    float Za = 0.f, Zb = 0.f;
    #pragma unroll 4
    for (int n = 0; n < 2048; n++) {
        float2 q = sq[n];
        float sa = fmaf(q.x, k0a, fmaf(q.y, k1a, -Ma));
        float sb = fmaf(q.x, k0b, fmaf(q.y, k1b, -Mb));
        float ea, eb;
        asm("ex2.approx.ftz.f32 %0, %1;" : "=f"(ea) : "f"(sa));
        asm("ex2.approx.ftz.f32 %0, %1;" : "=f"(eb) : "f"(sb));
        Za += ea; Zb += eb;
    }
    const float iZa = 1.f / Za, iZb = 1.f / Zb;
    g_nm[c * 2048 + ma] = -Ma;
    g_nm[c * 2048 + mb] = -Mb;
    g_vz[(c * 2048 + ma) * 2 + 0] = g_v[(c * 2048 + ma) * 2 + 0] * iZa;
    g_vz[(c * 2048 + ma) * 2 + 1] = g_v[(c * 2048 + ma) * 2 + 1] * iZa;
    g_vz[(c * 2048 + mb) * 2 + 0] = g_v[(c * 2048 + mb) * 2 + 0] * iZb;
    g_vz[(c * 2048 + mb) * 2 + 1] = g_v[(c * 2048 + mb) * 2 + 1] * iZb;
}

// =============================================================================
// Kernel C: out[c,n,b] += sum_{m in quarter} 2^(q.k - M) * vz[m,b]
// 4 n-rows per thread in registers: 2 LDS feed 4 exp elements.
// grid (2 nchunk, 4 mquarter, 32 c), 256 threads. 4 atomic contributors/output.
// =============================================================================
__global__ __launch_bounds__(256) void attn_out_kernel()
{
    __shared__ float4 ksm[512];   // (k0, k1, -M, pad)  8KB
    __shared__ float2 vzs[512];   //                    4KB
    const int t  = threadIdx.x;
    const int c  = blockIdx.z;
    const int m0 = blockIdx.y * 512;
    const int nb = blockIdx.x * 1024;

    for (int i = t; i < 512; i += 256) {
        const int m = m0 + i;
        ksm[i] = make_float4(g_k[(c * 2 + 0) * 2048 + m],
                             g_k[(c * 2 + 1) * 2048 + m],
                             g_nm[c * 2048 + m], 0.f);
        vzs[i] = ((const float2*)(g_vz + c * 4096))[m];
    }
    __syncthreads();

    const float2* qsrc = (const float2*)(g_q + c * 4096);
    const float2 q0 = qsrc[nb + t];
    const float2 q1 = qsrc[nb + t + 256];
    const float2 q2 = qsrc[nb + t + 512];
    const float2 q3 = qsrc[nb + t + 768];

    float a00 = 0.f, a01 = 0.f, a10 = 0.f, a11 = 0.f;
    float a20 = 0.f, a21 = 0.f, a30 = 0.f, a31 = 0.f;

    #pragma unroll 2
    for (int m = 0; m < 512; m++) {
        const float4 kk = ksm[m];
        const float2 vv = vzs[m];
        float s0 = fmaf(q0.x, kk.x, fmaf(q0.y, kk.y, kk.z));
        float s1 = fmaf(q1.x, kk.x, fmaf(q1.y, kk.y, kk.z));
        float s2 = fmaf(q2.x, kk.x, fmaf(q2.y, kk.y, kk.z));
        float s3 = fmaf(q3.x, kk.x, fmaf(q3.y, kk.y, kk.z));
        float e0, e1, e2, e3;
        asm("ex2.approx.ftz.f32 %0, %1;" : "=f"(e0) : "f"(s0));
        asm("ex2.approx.ftz.f32 %0, %1;" : "=f"(e1) : "f"(s1));
        asm("ex2.approx.ftz.f32 %0, %1;" : "=f"(e2) : "f"(s2));
        asm("ex2.approx.ftz.f32 %0, %1;" : "=f"(e3) : "f"(s3));
        a00 = fmaf(e0, vv.x, a00); a01 = fmaf(e0, vv.y, a01);
        a10 = fmaf(e1, vv.x, a10); a11 = fmaf(e1, vv.y, a11);
        a20 = fmaf(e2, vv.x, a20); a21 = fmaf(e2, vv.y, a21);
        a30 = fmaf(e3, vv.x, a30); a31 = fmaf(e3, vv.y, a31);
    }

    float* dst = g_attn + c * 4096;
    atomicAdd(&dst[(nb + t) * 2 + 0], a00);
    atomicAdd(&dst[(nb + t) * 2 + 1], a01);
    atomicAdd(&dst[(nb + t + 256) * 2 + 0], a10);
    atomicAdd(&dst[(nb + t + 256) * 2 + 1], a11);
    atomicAdd(&dst[(nb + t + 512) * 2 + 0], a20);
    atomicAdd(&dst[(nb + t + 512) * 2 + 1], a21);
    atomicAdd(&dst[(nb + t + 768) * 2 + 0], a30);
    atomicAdd(&dst[(nb + t + 768) * 2 + 1], a31);
}

// =============================================================================
// Kernel D: conv_alter (32 -> 64, 3x3x3, pad 1), split-K x8, accumulate into
// out (pre-initialized to x + bias). g_attn flat [C,N,B] viewed as [B,32,D,H,W].
// grid (cog=8, d=8, z=16: b*8 + s), 128 threads = 8 co x 16 h.
// =============================================================================
__global__ __launch_bounds__(128) void conv_alter_kernel(
    const float* __restrict__ wa, float* __restrict__ out)
{
    __shared__ float tile[3 * 18 * 20];
    const int t   = threadIdx.x;
    const int b   = blockIdx.z >> 3;
    const int s   = blockIdx.z & 7;       // ci chunk: [4s, 4s+4)
    const int d   = blockIdx.y;
    const int cog = blockIdx.x;
    const int co  = cog * 8 + (t >> 4);   // 0..63
    const int h   = t & 15;

    float acc[16];
    #pragma unroll
    for (int w = 0; w < 16; w++) acc[w] = 0.f;
    const float* Wc = wa + co * 32 * 27 + s * 4 * 27;

    for (int ci = 0; ci < 4; ci++) {
        const int cig = s * 4 + ci;
        __syncthreads();
        for (int i = t; i < 972; i += 128) {
            int dd = i / 324, r = i % 324, hh = r / 18, ww = r % 18;
            int gd = d + dd - 1, gh = hh - 1, gw = ww - 1;
            float val = 0.f;
            if ((unsigned)gd < 8u && (unsigned)gh < 16u && (unsigned)gw < 16u)
                val = g_attn[(b * 32 + cig) * 2048 + gd * 256 + gh * 16 + gw];
            tile[dd * 360 + hh * 20 + ww] = val;
        }
        __syncthreads();
        const float* Wci = Wc + ci * 27;
        #pragma unroll
        for (int kd = 0; kd < 3; kd++) {
            #pragma unroll
            for (int kh = 0; kh < 3; kh++) {
                const float* row = &tile[kd * 360 + (h + kh) * 20];
                float4 ra = ((const float4*)row)[0];
                float4 rb = ((const float4*)row)[1];
                float4 rc = ((const float4*)row)[2];
                float4 rd = ((const float4*)row)[3];
                float2 re = *(const float2*)(row + 16);
                float r0[18] = {ra.x, ra.y, ra.z, ra.w, rb.x, rb.y, rb.z, rb.w,
                                rc.x, rc.y, rc.z, rc.w, rd.x, rd.y, rd.z, rd.w,
                                re.x, re.y};
                const float w0 = Wci[(kd * 3 + kh) * 3 + 0];
                const float w1 = Wci[(kd * 3 + kh) * 3 + 1];
                const float w2 = Wci[(kd * 3 + kh) * 3 + 2];
                #pragma unroll
                for (int w = 0; w < 16; w++)
                    acc[w] = fmaf(w0, r0[w], fmaf(w1, r0[w + 1], fmaf(w2, r0[w + 2], acc[w])));
            }
        }
    }

    const int nbase = d * 256 + h * 16;
    #pragma unroll
    for (int w = 0; w < 16; w++)
        atomicAdd(&out[(b * 64 + co) * 2048 + nbase + w], acc[w]);
}

// =============================================================================
extern "C" void kernel_launch(void* const* d_in, const int* in_sizes, int n_in,
                              void* d_out, int out_size)
{
    const float* x  = (const float*)d_in[0];
    const float* wk = (const float*)d_in[1];
    const float* bk = (const float*)d_in[2];
    const float* bq = (const float*)d_in[4];
    const float* wq = (const float*)d_in[3];
    const float* wv = (const float*)d_in[5];
    const float* bv = (const float*)d_in[6];
    const float* wa = (const float*)d_in[7];
    const float* ba = (const float*)d_in[8];
    float* out = (float*)d_out;

    init_kernel<<<512, 256>>>(x, bk, bq, bv, ba, out);
    conv_qkv_kernel<<<dim3(8, 8, 8), 192>>>(x, wk, wq, wv);
    colstats_kernel<<<dim3(8, 32), 128>>>();
    attn_out_kernel<<<dim3(2, 4, 32), 256>>>();
    conv_alter_kernel<<<dim3(8, 8, 16), 128>>>(wa, out);
}

// round 6
// speedup vs baseline: 2.0266x; 1.0639x over previous
#include <cuda_runtime.h>

#define LOG2E 1.4426950408889634f

// ---------------- scratch (device globals; no allocation allowed) -------------
__device__ float g_k[32 * 2 * 2048];     // [c][b][n]           (raw)
__device__ float g_q[32 * 2048 * 2];     // [c][n][b]           (pre-scaled by LOG2E)
__device__ float g_v[32 * 2048 * 2];     // [c][n][b]
__device__ float g_vz[32 * 2048 * 2];    // v * (1/Z) per column
__device__ float g_nm[32 * 2048];        // -(box-bound max log2-logit) per (c,m)
__device__ float g_attn[32 * 2048 * 2];  // flat [C,N,B] attention output

// =============================================================================
// Kernel 0: init biases into qkv scratch, out = x + b_alter, zero g_attn.
// =============================================================================
__global__ __launch_bounds__(256) void init_kernel(
    const float* __restrict__ x,
    const float* __restrict__ bk, const float* __restrict__ bq,
    const float* __restrict__ bv, const float* __restrict__ ba,
    float* __restrict__ out)
{
    const int i = blockIdx.x * 256 + threadIdx.x;   // 512 blocks -> 131072 threads
    if (i < 131072) {
        const int c = i >> 12;
        g_k[i] = bk[c];
        g_q[i] = bq[c] * LOG2E;
        g_v[i] = bv[c];
    }
    for (int j = i; j < 262144; j += 131072) {
        const int co = (j >> 11) & 63;
        out[j] = x[j] + ba[co];
        g_attn[j] = 0.f;
    }
}

// =============================================================================
// Kernel A: conv3d key/query/value (64 -> 3x32 ch, 3x3x3, pad 1), split-K x4.
// grid (cog=8, d=8, z=8: b*4 + s), 192 threads = 12 co x 16 h.
// =============================================================================
__global__ __launch_bounds__(192) void conv_qkv_kernel(
    const float* __restrict__ x,
    const float* __restrict__ wk, const float* __restrict__ wq,
    const float* __restrict__ wv)
{
    __shared__ float tile[3 * 18 * 20];   // padded: [dd][hh][20]
    const int t   = threadIdx.x;
    const int b   = blockIdx.z >> 2;
    const int s   = blockIdx.z & 3;       // ci chunk: [16s, 16s+16)
    const int d   = blockIdx.y;
    const int cog = blockIdx.x;
    const int co  = cog * 12 + (t >> 4);  // 0..95
    const int h   = t & 15;
    const int which = co >> 5;            // 0=key 1=query 2=value
    const int c     = co & 31;

    const float* W = (which == 0) ? wk : (which == 1 ? wq : wv);
    float acc[16];
    #pragma unroll
    for (int w = 0; w < 16; w++) acc[w] = 0.f;

    const float* Wc = W + c * 64 * 27 + s * 16 * 27;

    for (int ci = 0; ci < 16; ci++) {
        const int cig = s * 16 + ci;
        __syncthreads();
        for (int i = t; i < 972; i += 192) {
            int dd = i / 324, r = i % 324, hh = r / 18, ww = r % 18;
            int gd = d + dd - 1, gh = hh - 1, gw = ww - 1;
            float val = 0.f;
            if ((unsigned)gd < 8u && (unsigned)gh < 16u && (unsigned)gw < 16u)
                val = x[(((b * 64 + cig) * 8 + gd) * 16 + gh) * 16 + gw];
            tile[dd * 360 + hh * 20 + ww] = val;
        }
        __syncthreads();
        const float* Wci = Wc + ci * 27;
        #pragma unroll
        for (int kd = 0; kd < 3; kd++) {
            #pragma unroll
            for (int kh = 0; kh < 3; kh++) {
                const float* row = &tile[kd * 360 + (h + kh) * 20];
                float4 ra = ((const float4*)row)[0];
                float4 rb = ((const float4*)row)[1];
                float4 rc = ((const float4*)row)[2];
                float4 rd = ((const float4*)row)[3];
                float2 re = *(const float2*)(row + 16);
                float r0[18] = {ra.x, ra.y, ra.z, ra.w, rb.x, rb.y, rb.z, rb.w,
                                rc.x, rc.y, rc.z, rc.w, rd.x, rd.y, rd.z, rd.w,
                                re.x, re.y};
                const float w0 = Wci[(kd * 3 + kh) * 3 + 0];
                const float w1 = Wci[(kd * 3 + kh) * 3 + 1];
                const float w2 = Wci[(kd * 3 + kh) * 3 + 2];
                #pragma unroll
                for (int w = 0; w < 16; w++)
                    acc[w] = fmaf(w0, r0[w], fmaf(w1, r0[w + 1], fmaf(w2, r0[w + 2], acc[w])));
            }
        }
    }

    const int nbase = d * 256 + h * 16;
    if (which == 0) {
        #pragma unroll
        for (int w = 0; w < 16; w++)
            atomicAdd(&g_k[(c * 2 + b) * 2048 + nbase + w], acc[w]);
    } else {
        float* dst = (which == 1) ? g_q : g_v;
        const float sc = (which == 1) ? LOG2E : 1.f;
        #pragma unroll
        for (int w = 0; w < 16; w++)
            atomicAdd(&dst[(c * 2048 + nbase + w) * 2 + b], acc[w] * sc);
    }
}

// =============================================================================
// Kernel B: per-column Z in log2 domain with BOX-BOUND shift (no max pass).
// 1 column per thread, 256-thread blocks -> 2048 warps chip-wide, MUFU-bound.
// grid (8 mchunk, c=32).
// =============================================================================
__global__ __launch_bounds__(256) void colstats_kernel()
{
    __shared__ float2 sq[2048];
    __shared__ float4 red[8];
    __shared__ float4 smm;
    const int t = threadIdx.x;
    const int c = blockIdx.y;
    const int m = blockIdx.x * 256 + t;

    const float2* qsrc = (const float2*)(g_q + c * 4096);
    float mxx = -1e30f, mnx = 1e30f, mxy = -1e30f, mny = 1e30f;
    for (int i = t; i < 2048; i += 256) {
        float2 q = qsrc[i];
        sq[i] = q;
        mxx = fmaxf(mxx, q.x); mnx = fminf(mnx, q.x);
        mxy = fmaxf(mxy, q.y); mny = fminf(mny, q.y);
    }
    #pragma unroll
    for (int off = 16; off; off >>= 1) {
        mxx = fmaxf(mxx, __shfl_xor_sync(~0u, mxx, off));
        mnx = fminf(mnx, __shfl_xor_sync(~0u, mnx, off));
        mxy = fmaxf(mxy, __shfl_xor_sync(~0u, mxy, off));
        mny = fminf(mny, __shfl_xor_sync(~0u, mny, off));
    }
    if ((t & 31) == 0) red[t >> 5] = make_float4(mxx, mnx, mxy, mny);
    __syncthreads();
    if (t == 0) {
        float4 a = red[0];
        #pragma unroll
        for (int w = 1; w < 8; w++) {
            float4 bb = red[w];
            a.x = fmaxf(a.x, bb.x); a.y = fminf(a.y, bb.y);
            a.z = fmaxf(a.z, bb.z); a.w = fminf(a.w, bb.w);
        }
        smm = a;
    }
    __syncthreads();

    const float4 mm = smm;
    const float k0 = g_k[(c * 2 + 0) * 2048 + m];
    const float k1 = g_k[(c * 2 + 1) * 2048 + m];
    const float M = fmaxf(k0 * mm.x, k0 * mm.y) + fmaxf(k1 * mm.z, k1 * mm.w);

    float Z = 0.f;
    #pragma unroll 8
    for (int n = 0; n < 2048; n++) {
        float2 q = sq[n];
        float sv = fmaf(q.x, k0, fmaf(q.y, k1, -M));
        float e;
        asm("ex2.approx.ftz.f32 %0, %1;" : "=f"(e) : "f"(sv));
        Z += e;
    }
    const float invZ = 1.f / Z;
    g_nm[c * 2048 + m] = -M;
    g_vz[(c * 2048 + m) * 2 + 0] = g_v[(c * 2048 + m) * 2 + 0] * invZ;
    g_vz[(c * 2048 + m) * 2 + 1] = g_v[(c * 2048 + m) * 2 + 1] * invZ;
}

// =============================================================================
// Kernel C: out[c,n,b] += sum_{m in chunk} 2^(q.k - M) * vz[m,b]
// 8 n-rows per thread (block covers all n); m-chunks of 228 -> grid = 32c x 9m
// = 288 blocks (97% SM balance). red.global.v2.f32 halves atomic instrs.
// =============================================================================
__global__ __launch_bounds__(256) void attn_out_kernel()
{
    __shared__ float4 ksm[228];   // (k0, k1, -M, pad)
    __shared__ float2 vzs[228];
    const int t   = threadIdx.x;
    const int bid = blockIdx.x;
    const int c   = bid / 9;
    const int mc  = bid % 9;
    const int m0  = mc * 228;
    const int mlen = (mc == 8) ? 224 : 228;

    if (t < mlen) {
        const int m = m0 + t;
        ksm[t] = make_float4(g_k[(c * 2 + 0) * 2048 + m],
                             g_k[(c * 2 + 1) * 2048 + m],
                             g_nm[c * 2048 + m], 0.f);
        vzs[t] = ((const float2*)(g_vz + c * 4096))[m];
    }
    __syncthreads();

    const float2* qsrc = (const float2*)(g_q + c * 4096);
    float2 q[8];
    #pragma unroll
    for (int r = 0; r < 8; r++) q[r] = qsrc[t + 256 * r];

    float ax[8], ay[8];
    #pragma unroll
    for (int r = 0; r < 8; r++) { ax[r] = 0.f; ay[r] = 0.f; }

    #pragma unroll 2
    for (int m = 0; m < mlen; m++) {
        const float4 kk = ksm[m];
        const float2 vv = vzs[m];
        #pragma unroll
        for (int r = 0; r < 8; r++) {
            float sv = fmaf(q[r].x, kk.x, fmaf(q[r].y, kk.y, kk.z));
            float e;
            asm("ex2.approx.ftz.f32 %0, %1;" : "=f"(e) : "f"(sv));
            ax[r] = fmaf(e, vv.x, ax[r]);
            ay[r] = fmaf(e, vv.y, ay[r]);
        }
    }

    float* dst = g_attn + c * 4096;
    #pragma unroll
    for (int r = 0; r < 8; r++) {
        float* p = dst + (t + 256 * r) * 2;
        asm volatile("red.global.add.v2.f32 [%0], {%1, %2};"
                     :: "l"(p), "f"(ax[r]), "f"(ay[r]) : "memory");
    }
}

// =============================================================================
// Kernel D: conv_alter (32 -> 64, 3x3x3, pad 1), split-K x8, accumulate into
// out (pre-initialized to x + bias). g_attn flat [C,N,B] viewed as [B,32,D,H,W].
// grid (cog=8, d=8, z=16: b*8 + s), 128 threads = 8 co x 16 h.
// =============================================================================
__global__ __launch_bounds__(128) void conv_alter_kernel(
    const float* __restrict__ wa, float* __restrict__ out)
{
    __shared__ float tile[3 * 18 * 20];
    const int t   = threadIdx.x;
    const int b   = blockIdx.z >> 3;
    const int s   = blockIdx.z & 7;       // ci chunk: [4s, 4s+4)
    const int d   = blockIdx.y;
    const int cog = blockIdx.x;
    const int co  = cog * 8 + (t >> 4);   // 0..63
    const int h   = t & 15;

    float acc[16];
    #pragma unroll
    for (int w = 0; w < 16; w++) acc[w] = 0.f;
    const float* Wc = wa + co * 32 * 27 + s * 4 * 27;

    for (int ci = 0; ci < 4; ci++) {
        const int cig = s * 4 + ci;
        __syncthreads();
        for (int i = t; i < 972; i += 128) {
            int dd = i / 324, r = i % 324, hh = r / 18, ww = r % 18;
            int gd = d + dd - 1, gh = hh - 1, gw = ww - 1;
            float val = 0.f;
            if ((unsigned)gd < 8u && (unsigned)gh < 16u && (unsigned)gw < 16u)
                val = g_attn[(b * 32 + cig) * 2048 + gd * 256 + gh * 16 + gw];
            tile[dd * 360 + hh * 20 + ww] = val;
        }
        __syncthreads();
        const float* Wci = Wc + ci * 27;
        #pragma unroll
        for (int kd = 0; kd < 3; kd++) {
            #pragma unroll
            for (int kh = 0; kh < 3; kh++) {
                const float* row = &tile[kd * 360 + (h + kh) * 20];
                float4 ra = ((const float4*)row)[0];
                float4 rb = ((const float4*)row)[1];
                float4 rc = ((const float4*)row)[2];
                float4 rd = ((const float4*)row)[3];
                float2 re = *(const float2*)(row + 16);
                float r0[18] = {ra.x, ra.y, ra.z, ra.w, rb.x, rb.y, rb.z, rb.w,
                                rc.x, rc.y, rc.z, rc.w, rd.x, rd.y, rd.z, rd.w,
                                re.x, re.y};
                const float w0 = Wci[(kd * 3 + kh) * 3 + 0];
                const float w1 = Wci[(kd * 3 + kh) * 3 + 1];
                const float w2 = Wci[(kd * 3 + kh) * 3 + 2];
                #pragma unroll
                for (int w = 0; w < 16; w++)
                    acc[w] = fmaf(w0, r0[w], fmaf(w1, r0[w + 1], fmaf(w2, r0[w + 2], acc[w])));
            }
        }
    }

    const int nbase = d * 256 + h * 16;
    #pragma unroll
    for (int w = 0; w < 16; w++)
        atomicAdd(&out[(b * 64 + co) * 2048 + nbase + w], acc[w]);
}

// =============================================================================
extern "C" void kernel_launch(void* const* d_in, const int* in_sizes, int n_in,
                              void* d_out, int out_size)
{
    const float* x  = (const float*)d_in[0];
    const float* wk = (const float*)d_in[1];
    const float* bk = (const float*)d_in[2];
    const float* wq = (const float*)d_in[3];
    const float* bq = (const float*)d_in[4];
    const float* wv = (const float*)d_in[5];
    const float* bv = (const float*)d_in[6];
    const float* wa = (const float*)d_in[7];
    const float* ba = (const float*)d_in[8];
    float* out = (float*)d_out;

    init_kernel<<<512, 256>>>(x, bk, bq, bv, ba, out);
    conv_qkv_kernel<<<dim3(8, 8, 8), 192>>>(x, wk, wq, wv);
    colstats_kernel<<<dim3(8, 32), 256>>>();
    attn_out_kernel<<<288, 256>>>();
    conv_alter_kernel<<<dim3(8, 8, 16), 128>>>(wa, out);
}